// round 2
// baseline (speedup 1.0000x reference)
#include <cuda_runtime.h>

#define HН 0
#define Hh 50
#define H 50
#define G4 200
#define BTOT 2048
#define TLEN 1024
#define BTILE 16
#define RB 4
#define NTH 256
#define XCH 32

// scratch for h1 between kernels (no cudaMalloc allowed)
__device__ float g_h1[BTOT * H];

__device__ __forceinline__ float sigf(float x) {
    // 1/(1+e^-x); safe at +-inf (fdividef(1, inf) -> 0)
    return __fdividef(1.0f, 1.0f + __expf(-x));
}
__device__ __forceinline__ float tanh_f(float x) {
    // 1 - 2/(e^{2x}+1); safe at +-inf
    return 1.0f - __fdividef(2.0f, __expf(2.0f * x) + 1.0f);
}

__global__ void __launch_bounds__(NTH) lstm1_kernel(
    const float* __restrict__ x,
    const float* __restrict__ Wih,
    const float* __restrict__ Whh,
    const float* __restrict__ bih,
    const float* __restrict__ bhh)
{
    __shared__ __align__(16) float Wsh[H][G4];        // [k][g] transposed
    __shared__ __align__(16) float hsh[2][H][BTILE];  // double-buffered h
    __shared__ __align__(16) float xsh[XCH][BTILE];   // x chunk

    const int tid = threadIdx.x;
    const int j = tid & 63;         // hidden index (padded to 64)
    const int bg = tid >> 6;        // batch group 0..3
    const int bbase = blockIdx.x * BTILE;
    const int bloc = bg * RB;       // 0,4,8,12

    // Load Whh transposed into shared: Wsh[k][g] = Whh[g*H + k]
    for (int i = tid; i < G4 * H; i += NTH) {
        int g = i / H, k = i - g * H;
        Wsh[k][g] = Whh[i];
    }
    // Zero initial h buffer
    for (int i = tid; i < H * BTILE; i += NTH) {
        (&hsh[0][0][0])[i] = 0.0f;
    }

    float bias0 = 0.f, bias1 = 0.f, bias2 = 0.f, bias3 = 0.f;
    float wi0 = 0.f, wi1 = 0.f, wi2 = 0.f, wi3 = 0.f;
    if (j < H) {
        bias0 = bih[j]         + bhh[j];
        bias1 = bih[H + j]     + bhh[H + j];
        bias2 = bih[2 * H + j] + bhh[2 * H + j];
        bias3 = bih[3 * H + j] + bhh[3 * H + j];
        wi0 = Wih[j];
        wi1 = Wih[H + j];
        wi2 = Wih[2 * H + j];
        wi3 = Wih[3 * H + j];
    }

    float c[RB], hv[RB];
#pragma unroll
    for (int r = 0; r < RB; r++) { c[r] = 0.f; hv[r] = 0.f; }

    __syncthreads();

    for (int t = 0; t < TLEN; t++) {
        if ((t & (XCH - 1)) == 0) {
            // previous-iteration barrier guarantees old xsh reads are done
            for (int i = tid; i < XCH * BTILE; i += NTH) {
                int tc = i >> 4, bl = i & 15;
                xsh[tc][bl] = x[(bbase + bl) * TLEN + t + tc];
            }
            __syncthreads();
        }
        const int buf = t & 1;
        if (j < H) {
            const float4 xv4 = *(const float4*)&xsh[t & (XCH - 1)][bloc];
            const float xv[RB] = {xv4.x, xv4.y, xv4.z, xv4.w};
            float a0[RB], a1[RB], a2[RB], a3[RB];
#pragma unroll
            for (int r = 0; r < RB; r++) {
                a0[r] = fmaf(xv[r], wi0, bias0);
                a1[r] = fmaf(xv[r], wi1, bias1);
                a2[r] = fmaf(xv[r], wi2, bias2);
                a3[r] = fmaf(xv[r], wi3, bias3);
            }
#pragma unroll
            for (int k = 0; k < H; k++) {
                const float w0 = Wsh[k][j];
                const float w1 = Wsh[k][H + j];
                const float w2 = Wsh[k][2 * H + j];
                const float w3 = Wsh[k][3 * H + j];
                const float4 h4 = *(const float4*)&hsh[buf][k][bloc];
                const float hr[RB] = {h4.x, h4.y, h4.z, h4.w};
#pragma unroll
                for (int r = 0; r < RB; r++) {
                    a0[r] = fmaf(hr[r], w0, a0[r]);
                    a1[r] = fmaf(hr[r], w1, a1[r]);
                    a2[r] = fmaf(hr[r], w2, a2[r]);
                    a3[r] = fmaf(hr[r], w3, a3[r]);
                }
            }
#pragma unroll
            for (int r = 0; r < RB; r++) {
                const float ig = sigf(a0[r]);
                const float fg = sigf(a1[r]);
                const float gg = tanh_f(a2[r]);
                const float og = sigf(a3[r]);
                c[r] = fmaf(fg, c[r], ig * gg);
                hv[r] = og * tanh_f(c[r]);
            }
            *(float4*)&hsh[buf ^ 1][j][bloc] =
                make_float4(hv[0], hv[1], hv[2], hv[3]);
        }
        __syncthreads();
    }

    if (j < H) {
#pragma unroll
        for (int r = 0; r < RB; r++)
            g_h1[(bbase + bloc + r) * H + j] = hv[r];
    }
}

__global__ void __launch_bounds__(NTH) lstm2_fc_kernel(
    const float* __restrict__ W2ih,
    const float* __restrict__ b2ih,
    const float* __restrict__ b2hh,
    const float* __restrict__ fcW,
    const float* __restrict__ fcb,
    float* __restrict__ out)
{
    __shared__ __align__(16) float Wsh[H][G4];
    __shared__ __align__(16) float h1sh[H][BTILE];
    __shared__ float h2sh[BTILE][H];

    const int tid = threadIdx.x;
    const int j = tid & 63;
    const int bg = tid >> 6;
    const int bbase = blockIdx.x * BTILE;
    const int bloc = bg * RB;

    for (int i = tid; i < G4 * H; i += NTH) {
        int g = i / H, k = i - g * H;
        Wsh[k][g] = W2ih[i];
    }
    for (int i = tid; i < H * BTILE; i += NTH) {
        int k = i >> 4, bl = i & 15;
        h1sh[k][bl] = g_h1[(bbase + bl) * H + k];
    }
    __syncthreads();

    if (j < H) {
        const float bias0 = b2ih[j]         + b2hh[j];
        const float bias1 = b2ih[H + j]     + b2hh[H + j];
        const float bias2 = b2ih[2 * H + j] + b2hh[2 * H + j];
        const float bias3 = b2ih[3 * H + j] + b2hh[3 * H + j];
        float a0[RB], a1[RB], a2[RB], a3[RB];
#pragma unroll
        for (int r = 0; r < RB; r++) {
            a0[r] = bias0; a1[r] = bias1; a2[r] = bias2; a3[r] = bias3;
        }
#pragma unroll
        for (int k = 0; k < H; k++) {
            const float w0 = Wsh[k][j];
            const float w1 = Wsh[k][H + j];
            const float w2 = Wsh[k][2 * H + j];
            const float w3 = Wsh[k][3 * H + j];
            const float4 h4 = *(const float4*)&h1sh[k][bloc];
            const float hr[RB] = {h4.x, h4.y, h4.z, h4.w};
#pragma unroll
            for (int r = 0; r < RB; r++) {
                a0[r] = fmaf(hr[r], w0, a0[r]);
                a1[r] = fmaf(hr[r], w1, a1[r]);
                a2[r] = fmaf(hr[r], w2, a2[r]);
                a3[r] = fmaf(hr[r], w3, a3[r]);
            }
        }
#pragma unroll
        for (int r = 0; r < RB; r++) {
            const float ig = sigf(a0[r]);
            (void)a1[r];                 // f-gate * c0(=0) contributes nothing
            const float gg = tanh_f(a2[r]);
            const float og = sigf(a3[r]);
            const float cc = ig * gg;    // c0 = 0
            h2sh[bloc + r][j] = og * tanh_f(cc);
        }
    }
    __syncthreads();

    if (tid < BTILE) {
        float s = fcb[0];
#pragma unroll
        for (int k = 0; k < H; k++)
            s = fmaf(h2sh[tid][k], fcW[k], s);
        out[bbase + tid] = s;
    }
}

extern "C" void kernel_launch(void* const* d_in, const int* in_sizes, int n_in,
                              void* d_out, int out_size)
{
    const float* x     = (const float*)d_in[0];
    const float* w1ih  = (const float*)d_in[1];
    const float* w1hh  = (const float*)d_in[2];
    const float* b1ih  = (const float*)d_in[3];
    const float* b1hh  = (const float*)d_in[4];
    const float* w2ih  = (const float*)d_in[5];
    // d_in[6] = lstm2_Whh: unused (layer-2 sees zero initial h)
    const float* b2ih  = (const float*)d_in[7];
    const float* b2hh  = (const float*)d_in[8];
    const float* fcW   = (const float*)d_in[9];
    const float* fcb   = (const float*)d_in[10];
    float* out = (float*)d_out;

    lstm1_kernel<<<BTOT / BTILE, NTH>>>(x, w1ih, w1hh, b1ih, b1hh);
    lstm2_fc_kernel<<<BTOT / BTILE, NTH>>>(w2ih, b2ih, b2hh, fcW, fcb, out);
}

// round 4
// speedup vs baseline: 1.1100x; 1.1100x over previous
#include <cuda_runtime.h>

#define H 50
#define BTOT 2048
#define TLEN 1024
#define BTILE 16
#define NTH 200
#define XCH 16
#define HP 20   // padded hsh row: 80B = odd multiple of 16B -> conflict-free strided 16B access

__device__ float g_h1[BTOT * H];

typedef unsigned long long u64;

__device__ __forceinline__ void ffma2(u64 &d, u64 a, u64 b) {
    asm("fma.rn.f32x2 %0, %1, %2, %0;" : "+l"(d) : "l"(a), "l"(b));
}
__device__ __forceinline__ u64 pack2(float lo, float hi) {
    u64 r; asm("mov.b64 %0, {%1, %2};" : "=l"(r) : "f"(lo), "f"(hi)); return r;
}
__device__ __forceinline__ u64 splat2(float x) {
    u64 r; asm("mov.b64 %0, {%1, %1};" : "=l"(r) : "f"(x)); return r;
}
__device__ __forceinline__ void unpack2(u64 v, float &lo, float &hi) {
    asm("mov.b64 {%0, %1}, %2;" : "=f"(lo), "=f"(hi) : "l"(v));
}

__device__ __forceinline__ float sigf(float x) {
    return __fdividef(1.0f, 1.0f + __expf(-x));
}
__device__ __forceinline__ float tanh_f(float x) {
    return 1.0f - __fdividef(2.0f, __expf(2.0f * x) + 1.0f);
}

// Layer 1: persistent recurrence. Block = 200 threads = 4 batch-groups x 50 hidden.
// Thread (j, bg) computes all 4 gates for hidden unit j, batches bloc..bloc+3.
// Gates packed in f32x2 pairs: acc0 = (i_pre, f_pre), acc1 = (g_pre, o_pre).
// Weight pairs prepacked in shared -> natural LDS.64, no per-k splat of weights.
__global__ void __launch_bounds__(NTH) lstm1_kernel(
    const float* __restrict__ x,
    const float* __restrict__ Wih,
    const float* __restrict__ Whh,
    const float* __restrict__ bih,
    const float* __restrict__ bhh)
{
    __shared__ __align__(16) float2 Wp0[H][H];       // [k][j] = (W_i[j][k], W_f[j][k])
    __shared__ __align__(16) float2 Wp1[H][H];       // [k][j] = (W_g[j][k], W_o[j][k])
    __shared__ __align__(16) float hsh[2][H][HP];    // double-buffered h, padded rows
    __shared__ __align__(16) float xsh[XCH][BTILE];  // x chunk

    const int tid = threadIdx.x;
    const int bg = tid / H;          // 0..3
    const int j  = tid - bg * H;     // 0..49, every thread active
    const int bbase = blockIdx.x * BTILE;
    const int bloc = bg * 4;

    // Prepack Whh gate-pairs into shared.
    for (int i = tid; i < 2 * H * H; i += NTH) {
        int p = i / (H * H);
        int rem = i - p * H * H;
        int k  = rem / H;
        int jj = rem - k * H;
        float lo = Whh[(p * 2 * H + jj) * H + k];      // p0: gate i row jj ; p1: gate g row 100+jj
        float hi = Whh[(p * 2 * H + H + jj) * H + k];  // p0: gate f row 50+jj ; p1: gate o row 150+jj
        if (p) Wp1[k][jj] = make_float2(lo, hi);
        else   Wp0[k][jj] = make_float2(lo, hi);
    }
    // Zero initial h buffer (both buffers incl. padding, cheap)
    for (int i = tid; i < 2 * H * HP; i += NTH)
        (&hsh[0][0][0])[i] = 0.0f;

    // Per-thread constants: bias pairs and Wih pairs (D=1 so Wih[g][0] = Wih[g])
    const u64 biasp0 = pack2(bih[j] + bhh[j],                 bih[H + j] + bhh[H + j]);
    const u64 biasp1 = pack2(bih[2 * H + j] + bhh[2 * H + j], bih[3 * H + j] + bhh[3 * H + j]);
    const u64 wip0 = pack2(Wih[j],         Wih[H + j]);
    const u64 wip1 = pack2(Wih[2 * H + j], Wih[3 * H + j]);

    float c[4]  = {0.f, 0.f, 0.f, 0.f};
    float hv[4] = {0.f, 0.f, 0.f, 0.f};

    __syncthreads();

    for (int t = 0; t < TLEN; t++) {
        if ((t & (XCH - 1)) == 0) {
            // previous end-of-step barrier guarantees old xsh reads are done
            for (int i = tid; i < XCH * BTILE; i += NTH) {
                int tc = i >> 4, bl = i & 15;
                xsh[tc][bl] = x[(bbase + bl) * TLEN + t + tc];
            }
            __syncthreads();
        }
        const int buf = t & 1;

        const float4 xq = *(const float4*)&xsh[t & (XCH - 1)][bloc];
        u64 xs[4] = {splat2(xq.x), splat2(xq.y), splat2(xq.z), splat2(xq.w)};

        u64 a0[4], a1[4];
#pragma unroll
        for (int r = 0; r < 4; r++) {
            a0[r] = biasp0; a1[r] = biasp1;
            ffma2(a0[r], xs[r], wip0);
            ffma2(a1[r], xs[r], wip1);
        }

#pragma unroll
        for (int k = 0; k < H; k++) {
            const u64 w0 = *(const u64*)&Wp0[k][j];
            const u64 w1 = *(const u64*)&Wp1[k][j];
            const float4 hq = *(const float4*)&hsh[buf][k][bloc];
            const u64 hs0 = splat2(hq.x), hs1 = splat2(hq.y),
                      hs2 = splat2(hq.z), hs3 = splat2(hq.w);
            ffma2(a0[0], hs0, w0); ffma2(a1[0], hs0, w1);
            ffma2(a0[1], hs1, w0); ffma2(a1[1], hs1, w1);
            ffma2(a0[2], hs2, w0); ffma2(a1[2], hs2, w1);
            ffma2(a0[3], hs3, w0); ffma2(a1[3], hs3, w1);
        }

#pragma unroll
        for (int r = 0; r < 4; r++) {
            float ip, fp, gp, op;
            unpack2(a0[r], ip, fp);
            unpack2(a1[r], gp, op);
            const float ig = sigf(ip);
            const float fg = sigf(fp);
            const float gg = tanh_f(gp);
            const float og = sigf(op);
            c[r]  = fmaf(fg, c[r], ig * gg);
            hv[r] = og * tanh_f(c[r]);
        }
        *(float4*)&hsh[buf ^ 1][j][bloc] = make_float4(hv[0], hv[1], hv[2], hv[3]);
        __syncthreads();
    }

#pragma unroll
    for (int r = 0; r < 4; r++)
        g_h1[(bbase + bloc + r) * H + j] = hv[r];
}

#define NTH2 256

__global__ void __launch_bounds__(NTH2) lstm2_fc_kernel(
    const float* __restrict__ W2ih,
    const float* __restrict__ b2ih,
    const float* __restrict__ b2hh,
    const float* __restrict__ fcW,
    const float* __restrict__ fcb,
    float* __restrict__ out)
{
    __shared__ __align__(16) float Wsh[H][4 * H];
    __shared__ __align__(16) float h1sh[H][BTILE];
    __shared__ float h2sh[BTILE][H];

    const int tid = threadIdx.x;
    const int j = tid & 63;
    const int bg = tid >> 6;
    const int bbase = blockIdx.x * BTILE;
    const int bloc = bg * 4;

    for (int i = tid; i < 4 * H * H; i += NTH2) {
        int g = i / H, k = i - g * H;
        Wsh[k][g] = W2ih[i];
    }
    for (int i = tid; i < H * BTILE; i += NTH2) {
        int k = i >> 4, bl = i & 15;
        h1sh[k][bl] = g_h1[(bbase + bl) * H + k];
    }
    __syncthreads();

    if (j < H) {
        const float bias0 = b2ih[j]         + b2hh[j];
        const float bias1 = b2ih[H + j]     + b2hh[H + j];
        const float bias2 = b2ih[2 * H + j] + b2hh[2 * H + j];
        const float bias3 = b2ih[3 * H + j] + b2hh[3 * H + j];
        float a0[4], a1[4], a2[4], a3[4];
#pragma unroll
        for (int r = 0; r < 4; r++) {
            a0[r] = bias0; a1[r] = bias1; a2[r] = bias2; a3[r] = bias3;
        }
#pragma unroll
        for (int k = 0; k < H; k++) {
            const float w0 = Wsh[k][j];
            const float w1 = Wsh[k][H + j];
            const float w2 = Wsh[k][2 * H + j];
            const float w3 = Wsh[k][3 * H + j];
            const float4 h4 = *(const float4*)&h1sh[k][bloc];
            const float hr[4] = {h4.x, h4.y, h4.z, h4.w};
#pragma unroll
            for (int r = 0; r < 4; r++) {
                a0[r] = fmaf(hr[r], w0, a0[r]);
                a1[r] = fmaf(hr[r], w1, a1[r]);
                a2[r] = fmaf(hr[r], w2, a2[r]);
                a3[r] = fmaf(hr[r], w3, a3[r]);
            }
        }
#pragma unroll
        for (int r = 0; r < 4; r++) {
            const float ig = sigf(a0[r]);
            (void)a1[r];                 // f-gate * c0(=0) contributes nothing
            const float gg = tanh_f(a2[r]);
            const float og = sigf(a3[r]);
            const float cc = ig * gg;    // c0 = 0
            h2sh[bloc + r][j] = og * tanh_f(cc);
        }
    }
    __syncthreads();

    if (tid < BTILE) {
        float s = fcb[0];
#pragma unroll
        for (int k = 0; k < H; k++)
            s = fmaf(h2sh[tid][k], fcW[k], s);
        out[bbase + tid] = s;
    }
}

extern "C" void kernel_launch(void* const* d_in, const int* in_sizes, int n_in,
                              void* d_out, int out_size)
{
    const float* x     = (const float*)d_in[0];
    const float* w1ih  = (const float*)d_in[1];
    const float* w1hh  = (const float*)d_in[2];
    const float* b1ih  = (const float*)d_in[3];
    const float* b1hh  = (const float*)d_in[4];
    const float* w2ih  = (const float*)d_in[5];
    // d_in[6] = lstm2_Whh: unused (layer-2 sees zero initial h)
    const float* b2ih  = (const float*)d_in[7];
    const float* b2hh  = (const float*)d_in[8];
    const float* fcW   = (const float*)d_in[9];
    const float* fcb   = (const float*)d_in[10];
    float* out = (float*)d_out;

    lstm1_kernel<<<BTOT / BTILE, NTH>>>(x, w1ih, w1hh, b1ih, b1hh);
    lstm2_fc_kernel<<<BTOT / BTILE, NTH2>>>(w2ih, b2ih, b2hh, fcW, fcb, out);
}